// round 6
// baseline (speedup 1.0000x reference)
#include <cuda_runtime.h>
#include <math_constants.h>

// Chamfer distance, B=16, N=M=4096, 3-D points.
// result = mean_n min_m d(x1_n, x2_m) + mean_m min_n d(x2_m, x1_n)
// d = |x|^2 + |y|^2 - 2 x.y, clamped at 0. sq1 and the clamp are folded
// outside the min loop (both commute with min).
// QPT=2, TPB=128 -> 512 blocks: trades a hair of issue efficiency
// (3.0 vs 2.75 cyc/pair) for 2x the resident warps (fixes issue=50.6%).

#define BATCH      16
#define NPTS       4096
#define CHUNK      1024        // targets staged per smem tile
#define TPB        128         // threads per block
#define QPT        2           // queries per thread
#define QPB        (TPB * QPT) // queries per block = 256
#define OUT_SCALE  (1.0f / 65536.0f)   // 1/(B*N), same for both directions

// ---- packed f32x2 helpers (sm_10x) -----------------------------------------
__device__ __forceinline__ unsigned long long pk2(float lo, float hi) {
    unsigned long long r;
    asm("mov.b64 %0, {%1, %2};" : "=l"(r) : "f"(lo), "f"(hi));
    return r;
}
__device__ __forceinline__ void unpk2(unsigned long long v, float& lo, float& hi) {
    asm("mov.b64 {%0, %1}, %2;" : "=f"(lo), "=f"(hi) : "l"(v));
}
__device__ __forceinline__ unsigned long long fma2(unsigned long long a,
                                                   unsigned long long b,
                                                   unsigned long long c) {
    unsigned long long d;
    asm("fma.rn.f32x2 %0, %1, %2, %3;" : "=l"(d) : "l"(a), "l"(b), "l"(c));
    return d;
}

__global__ void chamfer_zero_kernel(float* out) { out[0] = 0.0f; }

__global__ void __launch_bounds__(TPB)
chamfer_main_kernel(const float* __restrict__ xyz1,
                    const float* __restrict__ xyz2,
                    float* __restrict__ out) {
    __shared__ float sx[CHUNK];
    __shared__ float sy[CHUNK];
    __shared__ float sz[CHUNK];
    __shared__ float ss[CHUNK];
    __shared__ float red[4];

    const int dir = blockIdx.y;                 // 0: q=xyz1,t=xyz2; 1: swapped
    const int b   = blockIdx.x / (NPTS / QPB);
    const int qb  = blockIdx.x % (NPTS / QPB);
    const int tid = threadIdx.x;

    const float* qsrc = dir ? xyz2 : xyz1;
    const float* tsrc = dir ? xyz1 : xyz2;
    const float* tbase = tsrc + (size_t)b * NPTS * 3;

    // ---- per-thread query points (2, strided by TPB) ----
    const int q0 = qb * QPB + tid;
    const int q1 = q0 + TPB;
    const float* qp0 = qsrc + ((size_t)b * NPTS + q0) * 3;
    const float* qp1 = qsrc + ((size_t)b * NPTS + q1) * 3;
    const float ax = qp0[0], ay = qp0[1], az = qp0[2];
    const float bx = qp1[0], by = qp1[1], bz = qp1[2];
    const float sqa = fmaf(ax, ax, fmaf(ay, ay, az * az));
    const float sqb = fmaf(bx, bx, fmaf(by, by, bz * bz));

    const unsigned long long Ax = pk2(-2.0f * ax, -2.0f * ax);
    const unsigned long long Ay = pk2(-2.0f * ay, -2.0f * ay);
    const unsigned long long Az = pk2(-2.0f * az, -2.0f * az);
    const unsigned long long Bx = pk2(-2.0f * bx, -2.0f * bx);
    const unsigned long long By = pk2(-2.0f * by, -2.0f * by);
    const unsigned long long Bz = pk2(-2.0f * bz, -2.0f * bz);

    float a0 = CUDART_INF_F, a1 = CUDART_INF_F;
    float a2 = CUDART_INF_F, a3 = CUDART_INF_F;
    float b0 = CUDART_INF_F, b1 = CUDART_INF_F;
    float b2 = CUDART_INF_F, b3 = CUDART_INF_F;

    for (int c0 = 0; c0 < NPTS; c0 += CHUNK) {
        // ---- stage CHUNK targets into smem as SoA (x, y, z, |t|^2) ----
        for (int i = tid; i < CHUNK; i += TPB) {
            const float* t = tbase + (size_t)(c0 + i) * 3;
            float x = t[0], y = t[1], z = t[2];
            sx[i] = x;
            sy[i] = y;
            sz[i] = z;
            ss[i] = fmaf(x, x, fmaf(y, y, z * z));
        }
        __syncthreads();

        const float4* x4 = reinterpret_cast<const float4*>(sx);
        const float4* y4 = reinterpret_cast<const float4*>(sy);
        const float4* z4 = reinterpret_cast<const float4*>(sz);
        const float4* s4 = reinterpret_cast<const float4*>(ss);

        // ---- 4 targets x 2 queries per iteration, packed f32x2 FMAs ----
        #pragma unroll 4
        for (int j = 0; j < CHUNK / 4; ++j) {
            const float4 X = x4[j];
            const float4 Y = y4[j];
            const float4 Z = z4[j];
            const float4 S = s4[j];

            const unsigned long long X01 = pk2(X.x, X.y), X23 = pk2(X.z, X.w);
            const unsigned long long Y01 = pk2(Y.x, Y.y), Y23 = pk2(Y.z, Y.w);
            const unsigned long long Z01 = pk2(Z.x, Z.y), Z23 = pk2(Z.z, Z.w);
            const unsigned long long S01 = pk2(S.x, S.y), S23 = pk2(S.z, S.w);

            // query A: cand = sq2 - 2*(q . t)    (sqa added after the loop)
            unsigned long long ca01 = fma2(Az, Z01, S01);
            unsigned long long ca23 = fma2(Az, Z23, S23);
            ca01 = fma2(Ay, Y01, ca01);
            ca23 = fma2(Ay, Y23, ca23);
            ca01 = fma2(Ax, X01, ca01);
            ca23 = fma2(Ax, X23, ca23);

            // query B
            unsigned long long cb01 = fma2(Bz, Z01, S01);
            unsigned long long cb23 = fma2(Bz, Z23, S23);
            cb01 = fma2(By, Y01, cb01);
            cb23 = fma2(By, Y23, cb23);
            cb01 = fma2(Bx, X01, cb01);
            cb23 = fma2(Bx, X23, cb23);

            float lo, hi;
            unpk2(ca01, lo, hi); a0 = fminf(a0, lo); a1 = fminf(a1, hi);
            unpk2(ca23, lo, hi); a2 = fminf(a2, lo); a3 = fminf(a3, hi);
            unpk2(cb01, lo, hi); b0 = fminf(b0, lo); b1 = fminf(b1, hi);
            unpk2(cb23, lo, hi); b2 = fminf(b2, lo); b3 = fminf(b3, hi);
        }
        __syncthreads();
    }

    // dist = max(sq1 + min_m cand, 0), summed over this thread's 2 queries
    const float mina = fminf(fminf(a0, a1), fminf(a2, a3));
    const float minb = fminf(fminf(b0, b1), fminf(b2, b3));
    float v = fmaxf(sqa + mina, 0.0f) + fmaxf(sqb + minb, 0.0f);

    // ---- block reduction (4 warps) ----
    #pragma unroll
    for (int off = 16; off > 0; off >>= 1)
        v += __shfl_down_sync(0xffffffffu, v, off);
    const int warp = tid >> 5, lane = tid & 31;
    if (lane == 0) red[warp] = v;
    __syncthreads();
    if (warp == 0) {
        v = (lane < 4) ? red[lane] : 0.0f;
        #pragma unroll
        for (int off = 2; off > 0; off >>= 1)
            v += __shfl_down_sync(0xffffffffu, v, off);
        if (lane == 0) atomicAdd(out, v * OUT_SCALE);
    }
}

extern "C" void kernel_launch(void* const* d_in, const int* in_sizes, int n_in,
                              void* d_out, int out_size) {
    const float* xyz1 = (const float*)d_in[0];
    const float* xyz2 = (const float*)d_in[1];
    float* out = (float*)d_out;

    chamfer_zero_kernel<<<1, 1>>>(out);
    dim3 grid(BATCH * (NPTS / QPB), 2);
    chamfer_main_kernel<<<grid, TPB>>>(xyz1, xyz2, out);
}

// round 7
// speedup vs baseline: 1.3364x; 1.3364x over previous
#include <cuda_runtime.h>
#include <math_constants.h>

// Chamfer distance, B=16, N=M=4096, 3-D points.
// d = |x|^2 + |y|^2 - 2 x.y, clamped at 0; sq1 and clamp folded outside min.
// R4 inner loop (QPT=4, 2.75 cyc/pair, packed f32x2 FMAs) kept verbatim;
// occupancy fixed by TSPLIT=4 target-splitting: each block scans a 1024-target
// quarter and writes a partial min per query; a second kernel combines.

#define BATCH      16
#define NPTS       4096
#define TSPLIT     4
#define TCHUNK     (NPTS / TSPLIT)     // 1024 targets per block
#define TPB        128                 // threads per block (main)
#define QPT        4                   // queries per thread
#define QPB        (TPB * QPT)         // 512 queries per block
#define QTILES     (NPTS / QPB)        // 8
#define NQ_TOTAL   (2 * BATCH * NPTS)  // 131072 queries over both directions
#define OUT_SCALE  (1.0f / 65536.0f)   // 1/(B*N), same both directions

__device__ float g_partial[NQ_TOTAL * TSPLIT];   // 2 MB partial mins

// ---- packed f32x2 helpers (sm_10x) -----------------------------------------
__device__ __forceinline__ unsigned long long pk2(float lo, float hi) {
    unsigned long long r;
    asm("mov.b64 %0, {%1, %2};" : "=l"(r) : "f"(lo), "f"(hi));
    return r;
}
__device__ __forceinline__ void unpk2(unsigned long long v, float& lo, float& hi) {
    asm("mov.b64 {%0, %1}, %2;" : "=f"(lo), "=f"(hi) : "l"(v));
}
__device__ __forceinline__ unsigned long long fma2(unsigned long long a,
                                                   unsigned long long b,
                                                   unsigned long long c) {
    unsigned long long d;
    asm("fma.rn.f32x2 %0, %1, %2, %3;" : "=l"(d) : "l"(a), "l"(b), "l"(c));
    return d;
}

__global__ void chamfer_zero_kernel(float* out) { out[0] = 0.0f; }

__global__ void __launch_bounds__(TPB)
chamfer_main_kernel(const float* __restrict__ xyz1,
                    const float* __restrict__ xyz2) {
    __shared__ float sx[TCHUNK];
    __shared__ float sy[TCHUNK];
    __shared__ float sz[TCHUNK];
    __shared__ float ss[TCHUNK];

    const int dir = blockIdx.y;            // 0: q=xyz1,t=xyz2; 1: swapped
    const int ts  = blockIdx.z;            // target quarter
    const int b   = blockIdx.x / QTILES;
    const int qb  = blockIdx.x % QTILES;
    const int tid = threadIdx.x;

    const float* qsrc = dir ? xyz2 : xyz1;
    const float* tsrc = dir ? xyz1 : xyz2;
    const float* tbase = tsrc + ((size_t)b * NPTS + ts * TCHUNK) * 3;

    // ---- stage this block's 1024-target quarter as SoA (x, y, z, |t|^2) ----
    for (int i = tid; i < TCHUNK; i += TPB) {
        const float* t = tbase + (size_t)i * 3;
        float x = t[0], y = t[1], z = t[2];
        sx[i] = x;
        sy[i] = y;
        sz[i] = z;
        ss[i] = fmaf(x, x, fmaf(y, y, z * z));
    }

    // ---- per-thread query points (QPT, strided by TPB) ----
    unsigned long long Cx[QPT], Cy[QPT], Cz[QPT];
    #pragma unroll
    for (int k = 0; k < QPT; ++k) {
        const int qi = qb * QPB + tid + k * TPB;
        const float* qp = qsrc + ((size_t)b * NPTS + qi) * 3;
        const float qx = qp[0], qy = qp[1], qz = qp[2];
        Cx[k] = pk2(-2.0f * qx, -2.0f * qx);
        Cy[k] = pk2(-2.0f * qy, -2.0f * qy);
        Cz[k] = pk2(-2.0f * qz, -2.0f * qz);
    }

    float mn[QPT][4];
    #pragma unroll
    for (int k = 0; k < QPT; ++k)
        #pragma unroll
        for (int t = 0; t < 4; ++t) mn[k][t] = CUDART_INF_F;

    __syncthreads();

    const float4* x4 = reinterpret_cast<const float4*>(sx);
    const float4* y4 = reinterpret_cast<const float4*>(sy);
    const float4* z4 = reinterpret_cast<const float4*>(sz);
    const float4* s4 = reinterpret_cast<const float4*>(ss);

    // ---- 4 targets x QPT queries per iteration, packed f32x2 FMAs ----
    #pragma unroll 4
    for (int j = 0; j < TCHUNK / 4; ++j) {
        const float4 X = x4[j];
        const float4 Y = y4[j];
        const float4 Z = z4[j];
        const float4 S = s4[j];

        const unsigned long long X01 = pk2(X.x, X.y), X23 = pk2(X.z, X.w);
        const unsigned long long Y01 = pk2(Y.x, Y.y), Y23 = pk2(Y.z, Y.w);
        const unsigned long long Z01 = pk2(Z.x, Z.y), Z23 = pk2(Z.z, Z.w);
        const unsigned long long S01 = pk2(S.x, S.y), S23 = pk2(S.z, S.w);

        #pragma unroll
        for (int k = 0; k < QPT; ++k) {
            // cand = sq2 - 2*(q . t)   (sq1 folded in the final kernel)
            unsigned long long c01 = fma2(Cz[k], Z01, S01);
            unsigned long long c23 = fma2(Cz[k], Z23, S23);
            c01 = fma2(Cy[k], Y01, c01);
            c23 = fma2(Cy[k], Y23, c23);
            c01 = fma2(Cx[k], X01, c01);
            c23 = fma2(Cx[k], X23, c23);

            float lo, hi;
            unpk2(c01, lo, hi);
            mn[k][0] = fminf(mn[k][0], lo);
            mn[k][1] = fminf(mn[k][1], hi);
            unpk2(c23, lo, hi);
            mn[k][2] = fminf(mn[k][2], lo);
            mn[k][3] = fminf(mn[k][3], hi);
        }
    }

    // ---- write partial mins: slot (query, quarter) ----
    #pragma unroll
    for (int k = 0; k < QPT; ++k) {
        const int qi = qb * QPB + tid + k * TPB;
        const int qg = (dir * BATCH + b) * NPTS + qi;
        const float m = fminf(fminf(mn[k][0], mn[k][1]),
                              fminf(mn[k][2], mn[k][3]));
        g_partial[(size_t)qg * TSPLIT + ts] = m;
    }
}

#define FTPB 256
__global__ void __launch_bounds__(FTPB)
chamfer_final_kernel(const float* __restrict__ xyz1,
                     const float* __restrict__ xyz2,
                     float* __restrict__ out) {
    __shared__ float red[FTPB / 32];

    const int idx = blockIdx.x * FTPB + threadIdx.x;   // global query id
    const int dir = idx / (BATCH * NPTS);
    const int r   = idx % (BATCH * NPTS);
    const float* qsrc = dir ? xyz2 : xyz1;

    const float4 p = *reinterpret_cast<const float4*>(&g_partial[(size_t)idx * 4]);
    const float dmin = fminf(fminf(p.x, p.y), fminf(p.z, p.w));

    const float* qp = qsrc + (size_t)r * 3;
    const float qx = qp[0], qy = qp[1], qz = qp[2];
    const float sq = fmaf(qx, qx, fmaf(qy, qy, qz * qz));

    float v = fmaxf(sq + dmin, 0.0f);

    #pragma unroll
    for (int off = 16; off > 0; off >>= 1)
        v += __shfl_down_sync(0xffffffffu, v, off);
    const int warp = threadIdx.x >> 5, lane = threadIdx.x & 31;
    if (lane == 0) red[warp] = v;
    __syncthreads();
    if (warp == 0) {
        v = (lane < FTPB / 32) ? red[lane] : 0.0f;
        #pragma unroll
        for (int off = (FTPB / 64); off > 0; off >>= 1)
            v += __shfl_down_sync(0xffffffffu, v, off);
        if (lane == 0) atomicAdd(out, v * OUT_SCALE);
    }
}

extern "C" void kernel_launch(void* const* d_in, const int* in_sizes, int n_in,
                              void* d_out, int out_size) {
    const float* xyz1 = (const float*)d_in[0];
    const float* xyz2 = (const float*)d_in[1];
    float* out = (float*)d_out;

    chamfer_zero_kernel<<<1, 1>>>(out);
    dim3 grid(BATCH * QTILES, 2, TSPLIT);      // 128 x 2 x 4 = 1024 blocks
    chamfer_main_kernel<<<grid, TPB>>>(xyz1, xyz2);
    chamfer_final_kernel<<<NQ_TOTAL / FTPB, FTPB>>>(xyz1, xyz2, out);
}

// round 11
// speedup vs baseline: 1.3459x; 1.0071x over previous
#include <cuda_runtime.h>
#include <math_constants.h>

// Chamfer distance, B=16, N=M=4096, 3-D points — symmetric-sharing version.
// d(n,m) = |x1_n|^2 + |x2_m|^2 - 2 x1_n.x2_m computed ONCE per pair:
//   row-min (per n) accumulated in registers,
//   col-min (per m) via k-tree + clamp + warp redux.min.u32 + smem atomicMin.
// Partial mins (row: per tsplit-chunk, col: per qtile) combined by a final kernel.
// Clamp/min commute with the reference's per-element clamp (max(min,0)==min(max,0)).
// out[0] zeroed by the first main-kernel block (only the final kernel adds to it).

#define BATCH      16
#define NPTS       4096
#define TSPLIT     8
#define TCHUNK     (NPTS / TSPLIT)     // 512 targets per block
#define TPB        128
#define QPT        4
#define QPB        (TPB * QPT)         // 512 queries per block
#define QTILES     (NPTS / QPB)        // 8
#define OUT_SCALE  (1.0f / 65536.0f)   // 1/(B*N), same both directions

// row partial: min over this block's targets of full d (unclamped), per query
__device__ float        g_row[BATCH * QTILES * QPB * TSPLIT];
// col partial: min over this block's queries of clamped d (float bits), per target
__device__ unsigned int g_col[BATCH * TSPLIT * TCHUNK * QTILES];

// ---- packed f32x2 helpers (sm_10x) -----------------------------------------
__device__ __forceinline__ unsigned long long pk2(float lo, float hi) {
    unsigned long long r;
    asm("mov.b64 %0, {%1, %2};" : "=l"(r) : "f"(lo), "f"(hi));
    return r;
}
__device__ __forceinline__ void unpk2(unsigned long long v, float& lo, float& hi) {
    asm("mov.b64 {%0, %1}, %2;" : "=f"(lo), "=f"(hi) : "l"(v));
}
__device__ __forceinline__ unsigned long long fma2(unsigned long long a,
                                                   unsigned long long b,
                                                   unsigned long long c) {
    unsigned long long d;
    asm("fma.rn.f32x2 %0, %1, %2, %3;" : "=l"(d) : "l"(a), "l"(b), "l"(c));
    return d;
}
__device__ __forceinline__ unsigned long long add2(unsigned long long a,
                                                   unsigned long long b) {
    unsigned long long d;
    asm("add.rn.f32x2 %0, %1, %2;" : "=l"(d) : "l"(a), "l"(b));
    return d;
}

__global__ void __launch_bounds__(TPB)
chamfer_main_kernel(const float* __restrict__ xyz1,
                    const float* __restrict__ xyz2,
                    float* __restrict__ out) {
    __shared__ float        sx[TCHUNK];
    __shared__ float        sy[TCHUNK];
    __shared__ float        sz[TCHUNK];
    __shared__ float        ss[TCHUNK];
    __shared__ unsigned int scol[TCHUNK];

    const int ts  = blockIdx.y;            // target chunk
    const int b   = blockIdx.x / QTILES;
    const int qb  = blockIdx.x % QTILES;
    const int tid = threadIdx.x;
    const int lane = tid & 31;

    // zero the output ahead of the final kernel (stream-ordered after us)
    if (blockIdx.x == 0 && blockIdx.y == 0 && tid == 0) out[0] = 0.0f;

    const float* tbase = xyz2 + ((size_t)b * NPTS + ts * TCHUNK) * 3;

    // ---- stage this block's target chunk as SoA (x, y, z, |t|^2); init col mins
    for (int i = tid; i < TCHUNK; i += TPB) {
        const float* t = tbase + (size_t)i * 3;
        float x = t[0], y = t[1], z = t[2];
        sx[i] = x;
        sy[i] = y;
        sz[i] = z;
        ss[i] = fmaf(x, x, fmaf(y, y, z * z));
        scol[i] = 0x7F800000u;             // +inf
    }

    // ---- per-thread query points (QPT, strided by TPB) ----
    unsigned long long Cx[QPT], Cy[QPT], Cz[QPT], S1[QPT];
    #pragma unroll
    for (int k = 0; k < QPT; ++k) {
        const int qi = qb * QPB + tid + k * TPB;
        const float* qp = xyz1 + ((size_t)b * NPTS + qi) * 3;
        const float qx = qp[0], qy = qp[1], qz = qp[2];
        const float sq = fmaf(qx, qx, fmaf(qy, qy, qz * qz));
        Cx[k] = pk2(-2.0f * qx, -2.0f * qx);
        Cy[k] = pk2(-2.0f * qy, -2.0f * qy);
        Cz[k] = pk2(-2.0f * qz, -2.0f * qz);
        S1[k] = pk2(sq, sq);
    }

    float mn[QPT][4];
    #pragma unroll
    for (int k = 0; k < QPT; ++k)
        #pragma unroll
        for (int t = 0; t < 4; ++t) mn[k][t] = CUDART_INF_F;

    __syncthreads();

    const float4* x4 = reinterpret_cast<const float4*>(sx);
    const float4* y4 = reinterpret_cast<const float4*>(sy);
    const float4* z4 = reinterpret_cast<const float4*>(sz);
    const float4* s4 = reinterpret_cast<const float4*>(ss);

    // ---- 4 targets x QPT queries per iteration; each pair computed once ----
    #pragma unroll 4
    for (int j = 0; j < TCHUNK / 4; ++j) {
        const float4 X = x4[j];
        const float4 Y = y4[j];
        const float4 Z = z4[j];
        const float4 S = s4[j];

        const unsigned long long X01 = pk2(X.x, X.y), X23 = pk2(X.z, X.w);
        const unsigned long long Y01 = pk2(Y.x, Y.y), Y23 = pk2(Y.z, Y.w);
        const unsigned long long Z01 = pk2(Z.x, Z.y), Z23 = pk2(Z.z, Z.w);
        const unsigned long long S01 = pk2(S.x, S.y), S23 = pk2(S.z, S.w);

        float d[QPT][4];                   // full d per (query k, target t)
        #pragma unroll
        for (int k = 0; k < QPT; ++k) {
            unsigned long long c01 = fma2(Cz[k], Z01, S01);
            unsigned long long c23 = fma2(Cz[k], Z23, S23);
            c01 = fma2(Cy[k], Y01, c01);
            c23 = fma2(Cy[k], Y23, c23);
            c01 = fma2(Cx[k], X01, c01);
            c23 = fma2(Cx[k], X23, c23);
            c01 = add2(c01, S1[k]);        // d = cand + |q|^2
            c23 = add2(c23, S1[k]);
            unpk2(c01, d[k][0], d[k][1]);
            unpk2(c23, d[k][2], d[k][3]);
            mn[k][0] = fminf(mn[k][0], d[k][0]);
            mn[k][1] = fminf(mn[k][1], d[k][1]);
            mn[k][2] = fminf(mn[k][2], d[k][2]);
            mn[k][3] = fminf(mn[k][3], d[k][3]);
        }

        // column mins: reduce over this thread's queries, clamp, warp-reduce
        unsigned int uc0, uc1, uc2, uc3;
        {
            float c;
            c = fminf(fminf(d[0][0], d[1][0]), fminf(d[2][0], d[3][0]));
            uc0 = __reduce_min_sync(0xffffffffu, __float_as_uint(fmaxf(c, 0.0f)));
            c = fminf(fminf(d[0][1], d[1][1]), fminf(d[2][1], d[3][1]));
            uc1 = __reduce_min_sync(0xffffffffu, __float_as_uint(fmaxf(c, 0.0f)));
            c = fminf(fminf(d[0][2], d[1][2]), fminf(d[2][2], d[3][2]));
            uc2 = __reduce_min_sync(0xffffffffu, __float_as_uint(fmaxf(c, 0.0f)));
            c = fminf(fminf(d[0][3], d[1][3]), fminf(d[2][3], d[3][3]));
            uc3 = __reduce_min_sync(0xffffffffu, __float_as_uint(fmaxf(c, 0.0f)));
        }
        const unsigned int usel = (lane == 0) ? uc0
                                : (lane == 1) ? uc1
                                : (lane == 2) ? uc2 : uc3;
        if (lane < 4) atomicMin(&scol[j * 4 + lane], usel);
    }

    // ---- write row partials (unclamped d mins; clamped in final kernel) ----
    #pragma unroll
    for (int k = 0; k < QPT; ++k) {
        const float m = fminf(fminf(mn[k][0], mn[k][1]),
                              fminf(mn[k][2], mn[k][3]));
        const size_t qslot = (size_t)(b * QTILES + qb) * QPB + tid + k * TPB;
        g_row[qslot * TSPLIT + ts] = m;
    }

    __syncthreads();
    // ---- write col partials ----
    for (int i = tid; i < TCHUNK; i += TPB) {
        const size_t tslot = (size_t)(b * TSPLIT + ts) * TCHUNK + i;
        g_col[tslot * QTILES + qb] = scol[i];
    }
}

#define FTPB 256
#define NQ_TOTAL (2 * BATCH * NPTS)
__global__ void __launch_bounds__(FTPB)
chamfer_final_kernel(float* __restrict__ out) {
    __shared__ float red[FTPB / 32];

    const int idx = blockIdx.x * FTPB + threadIdx.x;
    float v;
    if (idx < BATCH * NPTS) {
        // n-side: min over TSPLIT row partials, then clamp (d already has sq1)
        const float4 r0 = *reinterpret_cast<const float4*>(&g_row[(size_t)idx * TSPLIT]);
        const float4 r1 = *reinterpret_cast<const float4*>(&g_row[(size_t)idx * TSPLIT + 4]);
        const float m = fminf(fminf(fminf(r0.x, r0.y), fminf(r0.z, r0.w)),
                              fminf(fminf(r1.x, r1.y), fminf(r1.z, r1.w)));
        v = fmaxf(m, 0.0f);
    } else {
        // m-side: min over QTILES col partials (already clamped, non-negative)
        const int t = idx - BATCH * NPTS;
        const uint4 u0 = *reinterpret_cast<const uint4*>(&g_col[(size_t)t * QTILES]);
        const uint4 u1 = *reinterpret_cast<const uint4*>(&g_col[(size_t)t * QTILES + 4]);
        // non-negative floats: uint order == float order
        unsigned int um = min(min(min(u0.x, u0.y), min(u0.z, u0.w)),
                              min(min(u1.x, u1.y), min(u1.z, u1.w)));
        v = __uint_as_float(um);
    }

    #pragma unroll
    for (int off = 16; off > 0; off >>= 1)
        v += __shfl_down_sync(0xffffffffu, v, off);
    const int warp = threadIdx.x >> 5, lane = threadIdx.x & 31;
    if (lane == 0) red[warp] = v;
    __syncthreads();
    if (warp == 0) {
        v = (lane < FTPB / 32) ? red[lane] : 0.0f;
        #pragma unroll
        for (int off = (FTPB / 64); off > 0; off >>= 1)
            v += __shfl_down_sync(0xffffffffu, v, off);
        if (lane == 0) atomicAdd(out, v * OUT_SCALE);
    }
}

extern "C" void kernel_launch(void* const* d_in, const int* in_sizes, int n_in,
                              void* d_out, int out_size) {
    const float* xyz1 = (const float*)d_in[0];
    const float* xyz2 = (const float*)d_in[1];
    float* out = (float*)d_out;

    dim3 grid(BATCH * QTILES, TSPLIT);         // 128 x 8 = 1024 blocks
    chamfer_main_kernel<<<grid, TPB>>>(xyz1, xyz2, out);
    chamfer_final_kernel<<<NQ_TOTAL / FTPB, FTPB>>>(out);
}

// round 14
// speedup vs baseline: 1.3464x; 1.0004x over previous
#include <cuda_runtime.h>
#include <math_constants.h>

// Chamfer distance, B=16, N=M=4096, 3-D points.
// d = |x|^2 + |y|^2 - 2 x.y, clamped at 0; sq1 and clamp folded outside min.
// R7 structure (QPT=4, packed f32x2 FMAs, 47 slots/512 pairs) with:
//   TSPLIT=8  -> 2048 blocks (halves last-wave raggedness),
//   out[0] zeroed by first main block (no separate zero kernel),
//   unroll 8 inner loop.

#define BATCH      16
#define NPTS       4096
#define TSPLIT     8
#define TCHUNK     (NPTS / TSPLIT)     // 512 targets per block
#define TPB        128                 // threads per block (main)
#define QPT        4                   // queries per thread
#define QPB        (TPB * QPT)         // 512 queries per block
#define QTILES     (NPTS / QPB)        // 8
#define NQ_TOTAL   (2 * BATCH * NPTS)  // 131072 queries over both directions
#define OUT_SCALE  (1.0f / 65536.0f)   // 1/(B*N), same both directions

__device__ float g_partial[NQ_TOTAL * TSPLIT];   // 4 MB partial mins

// ---- packed f32x2 helpers (sm_10x) -----------------------------------------
__device__ __forceinline__ unsigned long long pk2(float lo, float hi) {
    unsigned long long r;
    asm("mov.b64 %0, {%1, %2};" : "=l"(r) : "f"(lo), "f"(hi));
    return r;
}
__device__ __forceinline__ void unpk2(unsigned long long v, float& lo, float& hi) {
    asm("mov.b64 {%0, %1}, %2;" : "=f"(lo), "=f"(hi) : "l"(v));
}
__device__ __forceinline__ unsigned long long fma2(unsigned long long a,
                                                   unsigned long long b,
                                                   unsigned long long c) {
    unsigned long long d;
    asm("fma.rn.f32x2 %0, %1, %2, %3;" : "=l"(d) : "l"(a), "l"(b), "l"(c));
    return d;
}

__global__ void __launch_bounds__(TPB)
chamfer_main_kernel(const float* __restrict__ xyz1,
                    const float* __restrict__ xyz2,
                    float* __restrict__ out) {
    __shared__ float sx[TCHUNK];
    __shared__ float sy[TCHUNK];
    __shared__ float sz[TCHUNK];
    __shared__ float ss[TCHUNK];

    const int dir = blockIdx.y;            // 0: q=xyz1,t=xyz2; 1: swapped
    const int ts  = blockIdx.z;            // target chunk
    const int b   = blockIdx.x / QTILES;
    const int qb  = blockIdx.x % QTILES;
    const int tid = threadIdx.x;

    // zero the output ahead of the final kernel (stream-ordered after us)
    if (blockIdx.x == 0 && blockIdx.y == 0 && blockIdx.z == 0 && tid == 0)
        out[0] = 0.0f;

    const float* qsrc = dir ? xyz2 : xyz1;
    const float* tsrc = dir ? xyz1 : xyz2;
    const float* tbase = tsrc + ((size_t)b * NPTS + ts * TCHUNK) * 3;

    // ---- stage this block's target chunk as SoA (x, y, z, |t|^2) ----
    for (int i = tid; i < TCHUNK; i += TPB) {
        const float* t = tbase + (size_t)i * 3;
        float x = t[0], y = t[1], z = t[2];
        sx[i] = x;
        sy[i] = y;
        sz[i] = z;
        ss[i] = fmaf(x, x, fmaf(y, y, z * z));
    }

    // ---- per-thread query points (QPT, strided by TPB) ----
    unsigned long long Cx[QPT], Cy[QPT], Cz[QPT];
    #pragma unroll
    for (int k = 0; k < QPT; ++k) {
        const int qi = qb * QPB + tid + k * TPB;
        const float* qp = qsrc + ((size_t)b * NPTS + qi) * 3;
        const float qx = qp[0], qy = qp[1], qz = qp[2];
        Cx[k] = pk2(-2.0f * qx, -2.0f * qx);
        Cy[k] = pk2(-2.0f * qy, -2.0f * qy);
        Cz[k] = pk2(-2.0f * qz, -2.0f * qz);
    }

    float mn[QPT][4];
    #pragma unroll
    for (int k = 0; k < QPT; ++k)
        #pragma unroll
        for (int t = 0; t < 4; ++t) mn[k][t] = CUDART_INF_F;

    __syncthreads();

    const float4* x4 = reinterpret_cast<const float4*>(sx);
    const float4* y4 = reinterpret_cast<const float4*>(sy);
    const float4* z4 = reinterpret_cast<const float4*>(sz);
    const float4* s4 = reinterpret_cast<const float4*>(ss);

    // ---- 4 targets x QPT queries per iteration, packed f32x2 FMAs ----
    #pragma unroll 8
    for (int j = 0; j < TCHUNK / 4; ++j) {
        const float4 X = x4[j];
        const float4 Y = y4[j];
        const float4 Z = z4[j];
        const float4 S = s4[j];

        const unsigned long long X01 = pk2(X.x, X.y), X23 = pk2(X.z, X.w);
        const unsigned long long Y01 = pk2(Y.x, Y.y), Y23 = pk2(Y.z, Y.w);
        const unsigned long long Z01 = pk2(Z.x, Z.y), Z23 = pk2(Z.z, Z.w);
        const unsigned long long S01 = pk2(S.x, S.y), S23 = pk2(S.z, S.w);

        #pragma unroll
        for (int k = 0; k < QPT; ++k) {
            // cand = sq2 - 2*(q . t)   (sq1 folded in the final kernel)
            unsigned long long c01 = fma2(Cz[k], Z01, S01);
            unsigned long long c23 = fma2(Cz[k], Z23, S23);
            c01 = fma2(Cy[k], Y01, c01);
            c23 = fma2(Cy[k], Y23, c23);
            c01 = fma2(Cx[k], X01, c01);
            c23 = fma2(Cx[k], X23, c23);

            float lo, hi;
            unpk2(c01, lo, hi);
            mn[k][0] = fminf(mn[k][0], lo);
            mn[k][1] = fminf(mn[k][1], hi);
            unpk2(c23, lo, hi);
            mn[k][2] = fminf(mn[k][2], lo);
            mn[k][3] = fminf(mn[k][3], hi);
        }
    }

    // ---- write partial mins: slot (query, chunk) ----
    #pragma unroll
    for (int k = 0; k < QPT; ++k) {
        const int qi = qb * QPB + tid + k * TPB;
        const int qg = (dir * BATCH + b) * NPTS + qi;
        const float m = fminf(fminf(mn[k][0], mn[k][1]),
                              fminf(mn[k][2], mn[k][3]));
        g_partial[(size_t)qg * TSPLIT + ts] = m;
    }
}

#define FTPB 256
__global__ void __launch_bounds__(FTPB)
chamfer_final_kernel(const float* __restrict__ xyz1,
                     const float* __restrict__ xyz2,
                     float* __restrict__ out) {
    __shared__ float red[FTPB / 32];

    const int idx = blockIdx.x * FTPB + threadIdx.x;   // global query id
    const int dir = idx / (BATCH * NPTS);
    const int r   = idx % (BATCH * NPTS);
    const float* qsrc = dir ? xyz2 : xyz1;

    const float4 p0 = *reinterpret_cast<const float4*>(&g_partial[(size_t)idx * TSPLIT]);
    const float4 p1 = *reinterpret_cast<const float4*>(&g_partial[(size_t)idx * TSPLIT + 4]);
    const float dmin = fminf(fminf(fminf(p0.x, p0.y), fminf(p0.z, p0.w)),
                             fminf(fminf(p1.x, p1.y), fminf(p1.z, p1.w)));

    const float* qp = qsrc + (size_t)r * 3;
    const float qx = qp[0], qy = qp[1], qz = qp[2];
    const float sq = fmaf(qx, qx, fmaf(qy, qy, qz * qz));

    float v = fmaxf(sq + dmin, 0.0f);

    #pragma unroll
    for (int off = 16; off > 0; off >>= 1)
        v += __shfl_down_sync(0xffffffffu, v, off);
    const int warp = threadIdx.x >> 5, lane = threadIdx.x & 31;
    if (lane == 0) red[warp] = v;
    __syncthreads();
    if (warp == 0) {
        v = (lane < FTPB / 32) ? red[lane] : 0.0f;
        #pragma unroll
        for (int off = (FTPB / 64); off > 0; off >>= 1)
            v += __shfl_down_sync(0xffffffffu, v, off);
        if (lane == 0) atomicAdd(out, v * OUT_SCALE);
    }
}

extern "C" void kernel_launch(void* const* d_in, const int* in_sizes, int n_in,
                              void* d_out, int out_size) {
    const float* xyz1 = (const float*)d_in[0];
    const float* xyz2 = (const float*)d_in[1];
    float* out = (float*)d_out;

    dim3 grid(BATCH * QTILES, 2, TSPLIT);      // 128 x 2 x 8 = 2048 blocks
    chamfer_main_kernel<<<grid, TPB>>>(xyz1, xyz2, out);
    chamfer_final_kernel<<<NQ_TOTAL / FTPB, FTPB>>>(xyz1, xyz2, out);
}